// round 1
// baseline (speedup 1.0000x reference)
#include <cuda_runtime.h>
#include <math.h>
#include <float.h>

#define B   8
#define T_  8
#define C_  256
#define H_  56
#define W_  56
#define HW  3136      // 56*56
#define BT  64        // B*T_

// ---------------- scratch (device globals; no allocation allowed) ----------
__device__ float g_cmax [BT*HW];         // channel-pool max   [bt][h][w]
__device__ float g_cmean[BT*HW];         // channel-pool mean
__device__ float g_yc   [BT*HW];         // channel gate       [bt][h][w]
__device__ float g_tmax [B*C_*HW];       // T-pool max         [b][c][h][w]
__device__ float g_tmean[B*C_*HW];
__device__ float g_hmax [BT*C_*W_];      // H-pool max         [b][t][c][w]
__device__ float g_hmean[BT*C_*W_];
__device__ float g_wmax [BT*C_*H_];      // W-pool max         [b][t][c][h]
__device__ float g_wmean[BT*C_*H_];
__device__ float g_yt   [B*C_*HW];       // temporal gate      [b][c][h][w]
__device__ float g_yh   [BT*C_*W_];      // height gate        [b][t][c][w]
__device__ float g_yw   [BT*C_*H_];      // width gate         [b][t][c][h]

__device__ __forceinline__ float sigmoidf_(float z) {
    return 1.0f / (1.0f + expf(-z));
}

// ---------------- K1: channel pool (max/mean over C) -----------------------
// one thread per (bt, h, w); loop over c with stride HW (coalesced across warp)
__global__ void k_cpool(const float* __restrict__ x) {
    int idx = blockIdx.x * 256 + threadIdx.x;
    if (idx >= BT * HW) return;
    int bt = idx / HW;
    int p  = idx - bt * HW;
    const float* px = x + (size_t)bt * C_ * HW + p;
    float mx = -FLT_MAX, sm = 0.0f;
    #pragma unroll 8
    for (int c = 0; c < C_; ++c) {
        float v = __ldg(px + (size_t)c * HW);
        mx = fmaxf(mx, v);
        sm += v;
    }
    g_cmax[idx]  = mx;
    g_cmean[idx] = sm * (1.0f / C_);
}

// ---------------- K2: yc = sigmoid(bn(conv3d over (T,h,w)))) ---------------
__global__ void k_ycconv(const float* __restrict__ Wc,
                         const float* __restrict__ gam,
                         const float* __restrict__ bet) {
    int idx = blockIdx.x * 256 + threadIdx.x;
    if (idx >= BT * HW) return;
    int bt = idx / HW;
    int p  = idx - bt * HW;
    int b = bt >> 3, t = bt & 7;
    int h = p / W_, w = p - h * W_;
    float acc = 0.0f;
    #pragma unroll
    for (int kd = 0; kd < 3; ++kd) {
        int tt = t + kd - 1;
        if (tt < 0 || tt >= T_) continue;
        #pragma unroll
        for (int kh = 0; kh < 3; ++kh) {
            int hh = h + kh - 1;
            if (hh < 0 || hh >= H_) continue;
            #pragma unroll
            for (int kw = 0; kw < 3; ++kw) {
                int ww = w + kw - 1;
                if (ww < 0 || ww >= W_) continue;
                int q = (b * T_ + tt) * HW + hh * W_ + ww;
                acc += g_cmax[q]  * __ldg(Wc +      kd * 9 + kh * 3 + kw)
                     + g_cmean[q] * __ldg(Wc + 27 + kd * 9 + kh * 3 + kw);
            }
        }
    }
    float g = __ldg(gam + 0) * rsqrtf(1.0f + 1e-5f);
    g_yc[idx] = sigmoidf_(acc * g + __ldg(bet + 0));
}

// ---------------- K3: main pool pass ----------------------------------------
// block per (b,c). Reads 8 planes of x, gates by yc on the fly, produces:
//   tmax/tmean over t (kept in registers), hmax/hmean per w, wmax/wmean per h.
__global__ void k_mainpool(const float* __restrict__ x) {
    int bc = blockIdx.x;
    int b = bc >> 8, c = bc & 255;
    __shared__ float s[HW];
    int tid = threadIdx.x;
    float tmx[13], tsm[13];
    #pragma unroll
    for (int k = 0; k < 13; ++k) { tmx[k] = -FLT_MAX; tsm[k] = 0.0f; }

    for (int t = 0; t < T_; ++t) {
        const float* px  = x    + (size_t)((b * T_ + t) * C_ + c) * HW;
        const float* pyc = g_yc + (b * T_ + t) * HW;
        #pragma unroll
        for (int k = 0; k < 13; ++k) {
            int p = tid + k * 256;
            if (p < HW) {
                float v = px[p] * pyc[p];     // xc, never materialized in gmem
                s[p] = v;
                tmx[k] = fmaxf(tmx[k], v);
                tsm[k] += v;
            }
        }
        __syncthreads();
        int base = ((b * T_ + t) * C_ + c) * W_;   // W_ == H_ == 56
        if (tid < H_) {
            // reduce row h=tid over w  -> W-pool
            const float* row = s + tid * W_;
            float mx = -FLT_MAX, sm = 0.0f;
            #pragma unroll
            for (int w = 0; w < W_; ++w) { float v = row[w]; mx = fmaxf(mx, v); sm += v; }
            g_wmax[base + tid]  = mx;
            g_wmean[base + tid] = sm * (1.0f / W_);
        } else if (tid >= 64 && tid < 64 + W_) {
            // reduce column w over h -> H-pool
            int w = tid - 64;
            float mx = -FLT_MAX, sm = 0.0f;
            #pragma unroll
            for (int h = 0; h < H_; ++h) { float v = s[h * W_ + w]; mx = fmaxf(mx, v); sm += v; }
            g_hmax[base + w]  = mx;
            g_hmean[base + w] = sm * (1.0f / H_);
        }
        __syncthreads();
    }
    int obase = (b * C_ + c) * HW;
    #pragma unroll
    for (int k = 0; k < 13; ++k) {
        int p = tid + k * 256;
        if (p < HW) {
            g_tmax[obase + p]  = tmx[k];
            g_tmean[obase + p] = tsm[k] * (1.0f / T_);
        }
    }
}

// ---------------- K4a: yt conv over (c,h,w) ---------------------------------
// block per (b,c): smem caches 3 c-planes per input channel (split ch passes),
// each thread computes quads of 4 consecutive w outputs with register reuse.
__global__ void k_ytconv(const float* __restrict__ Wt,
                         const float* __restrict__ gam,
                         const float* __restrict__ bet) {
    int bc = blockIdx.x;
    int b = bc >> 8, c = bc & 255;
    __shared__ float s[3][HW];
    __shared__ float sw[54];
    int tid = threadIdx.x;
    if (tid < 54) sw[tid] = __ldg(Wt + tid);

    float acc[4][4];
    #pragma unroll
    for (int j = 0; j < 4; ++j)
        #pragma unroll
        for (int o = 0; o < 4; ++o) acc[j][o] = 0.0f;

    for (int ch = 0; ch < 2; ++ch) {
        const float* src = ch ? g_tmean : g_tmax;
        __syncthreads();                       // previous-pass readers done (+ sw visible)
        for (int dc = 0; dc < 3; ++dc) {
            int cc = c + dc - 1;
            bool cok = (cc >= 0) && (cc < C_);
            const float* plane = src + (size_t)(b * C_ + (cok ? cc : 0)) * HW;
            #pragma unroll
            for (int k = 0; k < 13; ++k) {
                int p = tid + k * 256;
                if (p < HW) s[dc][p] = cok ? plane[p] : 0.0f;
            }
        }
        __syncthreads();
        for (int j = 0; j < 4; ++j) {
            int g = tid + j * 256;
            if (g >= 784) break;               // 56 rows x 14 w-quads
            int h  = g / 14;
            int w0 = (g - h * 14) * 4;
            for (int dc = 0; dc < 3; ++dc) {
                #pragma unroll
                for (int kh = 0; kh < 3; ++kh) {
                    int hh = h + kh - 1;
                    bool hok = (hh >= 0) && (hh < H_);
                    float v[6];
                    #pragma unroll
                    for (int m = 0; m < 6; ++m) {
                        int ww = w0 - 1 + m;
                        v[m] = (hok && ww >= 0 && ww < W_) ? s[dc][hh * W_ + ww] : 0.0f;
                    }
                    #pragma unroll
                    for (int kw = 0; kw < 3; ++kw) {
                        float wt = sw[ch * 27 + dc * 9 + kh * 3 + kw];
                        #pragma unroll
                        for (int o = 0; o < 4; ++o) acc[j][o] += v[o + kw] * wt;
                    }
                }
            }
        }
    }
    float g2 = __ldg(gam + 1) * rsqrtf(1.0f + 1e-5f);
    float b2 = __ldg(bet + 1);
    int obase = (b * C_ + c) * HW;
    for (int j = 0; j < 4; ++j) {
        int g = tid + j * 256;
        if (g >= 784) break;
        int h  = g / 14;
        int w0 = (g - h * 14) * 4;
        #pragma unroll
        for (int o = 0; o < 4; ++o)
            g_yt[obase + h * W_ + w0 + o] = sigmoidf_(acc[j][o] * g2 + b2);
    }
}

// ---------------- K4b: yh conv over (T,c,w) ---------------------------------
__global__ void k_yhconv(const float* __restrict__ Wh,
                         const float* __restrict__ gam,
                         const float* __restrict__ bet) {
    int idx = blockIdx.x * 256 + threadIdx.x;
    if (idx >= BT * C_ * W_) return;
    int w   = idx % W_;
    int rem = idx / W_;
    int c   = rem % C_;
    int bt  = rem / C_;
    int b = bt >> 3, t = bt & 7;
    float acc = 0.0f;
    #pragma unroll
    for (int kd = 0; kd < 3; ++kd) {
        int tt = t + kd - 1;
        if (tt < 0 || tt >= T_) continue;
        #pragma unroll
        for (int kh = 0; kh < 3; ++kh) {
            int cc = c + kh - 1;
            if (cc < 0 || cc >= C_) continue;
            int base = ((b * T_ + tt) * C_ + cc) * W_;
            #pragma unroll
            for (int kw = 0; kw < 3; ++kw) {
                int ww = w + kw - 1;
                if (ww < 0 || ww >= W_) continue;
                acc += g_hmax[base + ww]  * __ldg(Wh +      kd * 9 + kh * 3 + kw)
                     + g_hmean[base + ww] * __ldg(Wh + 27 + kd * 9 + kh * 3 + kw);
            }
        }
    }
    float g2 = __ldg(gam + 2) * rsqrtf(1.0f + 1e-5f);
    g_yh[idx] = sigmoidf_(acc * g2 + __ldg(bet + 2));
}

// ---------------- K4c: yw conv over (T,h,c) ---------------------------------
// input (b,2,T,h,c) is g_wmax/g_wmean stored [b][t][c][h]; output stored [b][t][c][h]
__global__ void k_ywconv(const float* __restrict__ Ww,
                         const float* __restrict__ gam,
                         const float* __restrict__ bet) {
    int idx = blockIdx.x * 256 + threadIdx.x;
    if (idx >= BT * C_ * H_) return;
    int h   = idx % H_;
    int rem = idx / H_;
    int c   = rem % C_;
    int bt  = rem / C_;
    int b = bt >> 3, t = bt & 7;
    float acc = 0.0f;
    #pragma unroll
    for (int kd = 0; kd < 3; ++kd) {            // D = T
        int tt = t + kd - 1;
        if (tt < 0 || tt >= T_) continue;
        #pragma unroll
        for (int kh = 0; kh < 3; ++kh) {        // H = h
            int hh = h + kh - 1;
            if (hh < 0 || hh >= H_) continue;
            #pragma unroll
            for (int kw = 0; kw < 3; ++kw) {    // W = c
                int cc = c + kw - 1;
                if (cc < 0 || cc >= C_) continue;
                int q = ((b * T_ + tt) * C_ + cc) * H_ + hh;
                acc += g_wmax[q]  * __ldg(Ww +      kd * 9 + kh * 3 + kw)
                     + g_wmean[q] * __ldg(Ww + 27 + kd * 9 + kh * 3 + kw);
            }
        }
    }
    float g2 = __ldg(gam + 3) * rsqrtf(1.0f + 1e-5f);
    g_yw[idx] = sigmoidf_(acc * g2 + __ldg(bet + 3));
}

// ---------------- K5: broadcast-combine -> out -------------------------------
// out[bt,c,h,w] = (yt[b,c,h,w] + yh[b,t,c,w] + yw[b,t,c,h]) / 3, float4 stores
__global__ void k_combine(float* __restrict__ out) {
    int gid = blockIdx.x * 256 + threadIdx.x;   // one float4 per thread
    if (gid >= BT * C_ * 784) return;
    int q     = gid % 784;
    int plane = gid / 784;
    int c  = plane % C_;
    int bt = plane / C_;
    int b = bt >> 3, t = bt & 7;
    int h  = q / 14;
    int w0 = (q - h * 14) * 4;

    const float4 yt4 = *(const float4*)(g_yt + (b * C_ + c) * HW + h * W_ + w0);
    const float4 yh4 = *(const float4*)(g_yh + ((b * T_ + t) * C_ + c) * W_ + w0);
    float yws = g_yw[((b * T_ + t) * C_ + c) * H_ + h];

    const float s3 = 1.0f / 3.0f;
    float4 o;
    o.x = (yt4.x + yh4.x + yws) * s3;
    o.y = (yt4.y + yh4.y + yws) * s3;
    o.z = (yt4.z + yh4.z + yws) * s3;
    o.w = (yt4.w + yh4.w + yws) * s3;
    ((float4*)out)[gid] = o;
}

// ---------------- launch -----------------------------------------------------
extern "C" void kernel_launch(void* const* d_in, const int* in_sizes, int n_in,
                              void* d_out, int out_size) {
    const float* x   = (const float*)d_in[0];
    const float* Wc  = (const float*)d_in[1];
    const float* Wt  = (const float*)d_in[2];
    const float* Wh  = (const float*)d_in[3];
    const float* Ww  = (const float*)d_in[4];
    const float* gam = (const float*)d_in[5];
    const float* bet = (const float*)d_in[6];
    float* out = (float*)d_out;

    k_cpool   <<<(BT * HW + 255) / 256, 256>>>(x);
    k_ycconv  <<<(BT * HW + 255) / 256, 256>>>(Wc, gam, bet);
    k_mainpool<<<B * C_, 256>>>(x);
    k_ytconv  <<<B * C_, 256>>>(Wt, gam, bet);
    k_yhconv  <<<(BT * C_ * W_ + 255) / 256, 256>>>(Wh, gam, bet);
    k_ywconv  <<<(BT * C_ * H_ + 255) / 256, 256>>>(Ww, gam, bet);
    k_combine <<<(BT * C_ * 784 + 255) / 256, 256>>>(out);
}

// round 3
// speedup vs baseline: 1.2096x; 1.2096x over previous
#include <cuda_runtime.h>
#include <math.h>
#include <float.h>

#define B   8
#define T_  8
#define C_  256
#define H_  56
#define W_  56
#define HW  3136      // 56*56
#define BT  64        // B*T_

// ---------------- scratch (device globals; no allocation allowed) ----------
__device__ float g_cmax [BT*HW];         // channel-pool max   [bt][h][w]
__device__ float g_cmean[BT*HW];         // channel-pool mean
__device__ float g_yc   [BT*HW];         // channel gate       [bt][h][w]
__device__ float g_tmax [B*C_*HW];       // T-pool max         [b][c][h][w]
__device__ float g_tmean[B*C_*HW];
__device__ float g_hmax [BT*C_*W_];      // H-pool max         [b][t][c][w]
__device__ float g_hmean[BT*C_*W_];
__device__ float g_wmax [BT*C_*H_];      // W-pool max         [b][t][c][h]
__device__ float g_wmean[BT*C_*H_];
__device__ float g_yt   [B*C_*HW];       // temporal gate      [b][c][h][w]
__device__ float g_yh   [BT*C_*W_];      // height gate        [b][t][c][w]
__device__ float g_yw   [BT*C_*H_];      // width gate         [b][t][c][h]

__device__ __forceinline__ float sigmoidf_(float z) {
    return 1.0f / (1.0f + expf(-z));
}

// ---------------- K1: channel pool (max/mean over C) -----------------------
__global__ void k_cpool(const float* __restrict__ x) {
    int idx = blockIdx.x * 256 + threadIdx.x;
    if (idx >= BT * HW) return;
    int bt = idx / HW;
    int p  = idx - bt * HW;
    const float* px = x + (size_t)bt * C_ * HW + p;
    float mx = -FLT_MAX, sm = 0.0f;
    #pragma unroll 8
    for (int c = 0; c < C_; ++c) {
        float v = __ldg(px + (size_t)c * HW);
        mx = fmaxf(mx, v);
        sm += v;
    }
    g_cmax[idx]  = mx;
    g_cmean[idx] = sm * (1.0f / C_);
}

// ---------------- K2: yc = sigmoid(bn(conv3d over (T,h,w)))) ---------------
__global__ void k_ycconv(const float* __restrict__ Wc,
                         const float* __restrict__ gam,
                         const float* __restrict__ bet) {
    int idx = blockIdx.x * 256 + threadIdx.x;
    if (idx >= BT * HW) return;
    int bt = idx / HW;
    int p  = idx - bt * HW;
    int b = bt >> 3, t = bt & 7;
    int h = p / W_, w = p - h * W_;
    float acc = 0.0f;
    #pragma unroll
    for (int kd = 0; kd < 3; ++kd) {
        int tt = t + kd - 1;
        if (tt < 0 || tt >= T_) continue;
        #pragma unroll
        for (int kh = 0; kh < 3; ++kh) {
            int hh = h + kh - 1;
            if (hh < 0 || hh >= H_) continue;
            #pragma unroll
            for (int kw = 0; kw < 3; ++kw) {
                int ww = w + kw - 1;
                if (ww < 0 || ww >= W_) continue;
                int q = (b * T_ + tt) * HW + hh * W_ + ww;
                acc += g_cmax[q]  * __ldg(Wc +      kd * 9 + kh * 3 + kw)
                     + g_cmean[q] * __ldg(Wc + 27 + kd * 9 + kh * 3 + kw);
            }
        }
    }
    float g = __ldg(gam + 0) * rsqrtf(1.0f + 1e-5f);
    g_yc[idx] = sigmoidf_(acc * g + __ldg(bet + 0));
}

// ---------------- K3: main pool pass ----------------------------------------
__global__ void k_mainpool(const float* __restrict__ x) {
    int bc = blockIdx.x;
    int b = bc >> 8, c = bc & 255;
    __shared__ float s[HW];
    int tid = threadIdx.x;
    float tmx[13], tsm[13];
    #pragma unroll
    for (int k = 0; k < 13; ++k) { tmx[k] = -FLT_MAX; tsm[k] = 0.0f; }

    for (int t = 0; t < T_; ++t) {
        const float* px  = x    + (size_t)((b * T_ + t) * C_ + c) * HW;
        const float* pyc = g_yc + (b * T_ + t) * HW;
        #pragma unroll
        for (int k = 0; k < 13; ++k) {
            int p = tid + k * 256;
            if (p < HW) {
                float v = px[p] * pyc[p];     // xc, never materialized in gmem
                s[p] = v;
                tmx[k] = fmaxf(tmx[k], v);
                tsm[k] += v;
            }
        }
        __syncthreads();
        int base = ((b * T_ + t) * C_ + c) * W_;
        if (tid < H_) {
            const float* row = s + tid * W_;
            float mx = -FLT_MAX, sm = 0.0f;
            #pragma unroll
            for (int w = 0; w < W_; ++w) { float v = row[w]; mx = fmaxf(mx, v); sm += v; }
            g_wmax[base + tid]  = mx;
            g_wmean[base + tid] = sm * (1.0f / W_);
        } else if (tid >= 64 && tid < 64 + W_) {
            int w = tid - 64;
            float mx = -FLT_MAX, sm = 0.0f;
            #pragma unroll
            for (int h = 0; h < H_; ++h) { float v = s[h * W_ + w]; mx = fmaxf(mx, v); sm += v; }
            g_hmax[base + w]  = mx;
            g_hmean[base + w] = sm * (1.0f / H_);
        }
        __syncthreads();
    }
    int obase = (b * C_ + c) * HW;
    #pragma unroll
    for (int k = 0; k < 13; ++k) {
        int p = tid + k * 256;
        if (p < HW) {
            g_tmax[obase + p]  = tmx[k];
            g_tmean[obase + p] = tsm[k] * (1.0f / T_);
        }
    }
}

// ---------------- K4a: yt conv over (c,h,w) ---------------------------------
// block per (b,c). Padded halo plane in smem (58x58, conflict-free columns).
// thread = one w column x 14-high output strip; slide 16 rows, each row feeds
// 3 kh taps into constant-indexed accumulators.
__global__ void k_ytconv(const float* __restrict__ Wt,
                         const float* __restrict__ gam,
                         const float* __restrict__ bet) {
    int bc = blockIdx.x;
    int b = bc >> 8, c = bc & 255;
    __shared__ float s[58 * 58];
    __shared__ float sw[54];
    int tid  = threadIdx.x;
    int w    = tid & 63;
    int hseg = tid >> 6;          // 0..3
    int h0   = hseg * 14;
    if (tid < 54) sw[tid] = __ldg(Wt + tid);

    float acc[14];
    #pragma unroll
    for (int i = 0; i < 14; ++i) acc[i] = 0.0f;

    for (int ch = 0; ch < 2; ++ch) {
        const float* src = ch ? g_tmean : g_tmax;
        for (int dc = 0; dc < 3; ++dc) {
            int cc = c + dc - 1;
            if (cc < 0 || cc >= C_) continue;
            const float* plane = src + (size_t)(b * C_ + cc) * HW;
            __syncthreads();
            for (int i = tid; i < 58 * 58; i += 256) {
                int r  = i / 58, cl = i - r * 58;
                int hh = r - 1,  ww = cl - 1;
                s[i] = (hh >= 0 && hh < H_ && ww >= 0 && ww < W_)
                         ? plane[hh * W_ + ww] : 0.0f;
            }
            __syncthreads();
            if (w < W_) {
                const float* wp = sw + ch * 27 + dc * 9;
                float w00 = wp[0], w01 = wp[1], w02 = wp[2];
                float w10 = wp[3], w11 = wp[4], w12 = wp[5];
                float w20 = wp[6], w21 = wp[7], w22 = wp[8];
                #pragma unroll
                for (int r = 0; r < 16; ++r) {
                    const float* row = s + (h0 + r) * 58 + w;
                    float v0 = row[0], v1 = row[1], v2 = row[2];
                    float d0 = w00 * v0 + w01 * v1 + w02 * v2;   // kh=0
                    float d1 = w10 * v0 + w11 * v1 + w12 * v2;   // kh=1
                    float d2 = w20 * v0 + w21 * v1 + w22 * v2;   // kh=2
                    if (r      < 14)            acc[r]     += d0;
                    if (r - 1 >= 0 && r - 1 < 14) acc[r - 1] += d1;
                    if (r - 2 >= 0)             acc[r - 2] += d2;
                }
            }
        }
    }
    if (w < W_) {
        float g2 = __ldg(gam + 1) * rsqrtf(1.0f + 1e-5f);
        float b2 = __ldg(bet + 1);
        float* out = g_yt + (b * C_ + c) * HW;
        #pragma unroll
        for (int i = 0; i < 14; ++i)
            out[(h0 + i) * W_ + w] = sigmoidf_(acc[i] * g2 + b2);
    }
}

// ---------------- K4b: yh conv over (T,c,w) ---------------------------------
// block per (b,t,ctile16). smem tile 18(c) x 58(w), slide along c; thread=w col.
__global__ void k_yhconv(const float* __restrict__ Wh,
                         const float* __restrict__ gam,
                         const float* __restrict__ bet) {
    int bid = blockIdx.x;
    int ct = bid & 15, t = (bid >> 4) & 7, b = bid >> 7;
    int c0 = ct * 16;
    __shared__ float s[18 * 58];
    __shared__ float sw[54];
    int tid  = threadIdx.x;
    int w    = tid & 63;
    int cseg = tid >> 6;          // 0..3 -> 4 c each
    if (tid < 54) sw[tid] = __ldg(Wh + tid);

    float acc[4];
    #pragma unroll
    for (int j = 0; j < 4; ++j) acc[j] = 0.0f;

    for (int ch = 0; ch < 2; ++ch) {
        const float* src = ch ? g_hmean : g_hmax;
        for (int kd = 0; kd < 3; ++kd) {
            int tt = t + kd - 1;
            if (tt < 0 || tt >= T_) continue;
            const float* pl = src + (size_t)(b * T_ + tt) * C_ * W_;
            __syncthreads();
            for (int i = tid; i < 18 * 58; i += 256) {
                int r  = i / 58, cl = i - r * 58;
                int cc = c0 - 1 + r, ww = cl - 1;
                s[i] = (cc >= 0 && cc < C_ && ww >= 0 && ww < W_)
                         ? pl[cc * W_ + ww] : 0.0f;
            }
            __syncthreads();
            if (w < W_) {
                const float* wp = sw + ch * 27 + kd * 9;
                float w00 = wp[0], w01 = wp[1], w02 = wp[2];
                float w10 = wp[3], w11 = wp[4], w12 = wp[5];
                float w20 = wp[6], w21 = wp[7], w22 = wp[8];
                #pragma unroll
                for (int r = 0; r < 6; ++r) {
                    const float* row = s + (cseg * 4 + r) * 58 + w;
                    float v0 = row[0], v1 = row[1], v2 = row[2];
                    float d0 = w00 * v0 + w01 * v1 + w02 * v2;   // kh=0
                    float d1 = w10 * v0 + w11 * v1 + w12 * v2;
                    float d2 = w20 * v0 + w21 * v1 + w22 * v2;
                    if (r      < 4)             acc[r]     += d0;
                    if (r - 1 >= 0 && r - 1 < 4) acc[r - 1] += d1;
                    if (r - 2 >= 0)             acc[r - 2] += d2;
                }
            }
        }
    }
    if (w < W_) {
        float g2 = __ldg(gam + 2) * rsqrtf(1.0f + 1e-5f);
        float b2 = __ldg(bet + 2);
        #pragma unroll
        for (int j = 0; j < 4; ++j) {
            int c = c0 + cseg * 4 + j;
            g_yh[((b * T_ + t) * C_ + c) * W_ + w] = sigmoidf_(acc[j] * g2 + b2);
        }
    }
}

// ---------------- K4c: yw conv over (T,h,c) ---------------------------------
// input/out stored [b][t][c][h]; conv dims (kd=t, kh=h, kw=c).
// block per (b,t,ctile16). smem tile 18(c) x 58(h); thread = h column.
__global__ void k_ywconv(const float* __restrict__ Ww,
                         const float* __restrict__ gam,
                         const float* __restrict__ bet) {
    int bid = blockIdx.x;
    int ct = bid & 15, t = (bid >> 4) & 7, b = bid >> 7;
    int c0 = ct * 16;
    __shared__ float s[18 * 58];
    __shared__ float sw[54];
    int tid  = threadIdx.x;
    int h    = tid & 63;
    int cseg = tid >> 6;
    if (tid < 54) sw[tid] = __ldg(Ww + tid);

    float acc[4];
    #pragma unroll
    for (int j = 0; j < 4; ++j) acc[j] = 0.0f;

    for (int ch = 0; ch < 2; ++ch) {
        const float* src = ch ? g_wmean : g_wmax;
        for (int kd = 0; kd < 3; ++kd) {
            int tt = t + kd - 1;
            if (tt < 0 || tt >= T_) continue;
            const float* pl = src + (size_t)(b * T_ + tt) * C_ * H_;
            __syncthreads();
            for (int i = tid; i < 18 * 58; i += 256) {
                int r  = i / 58, cl = i - r * 58;
                int cc = c0 - 1 + r, hh = cl - 1;
                s[i] = (cc >= 0 && cc < C_ && hh >= 0 && hh < H_)
                         ? pl[cc * H_ + hh] : 0.0f;
            }
            __syncthreads();
            if (h < H_) {
                const float* wp = sw + ch * 27 + kd * 9;
                // d per kw: sum over kh of W[kd][kh][kw] * v[kh]
                float w00 = wp[0], w01 = wp[1], w02 = wp[2];   // kh=0, kw=0..2
                float w10 = wp[3], w11 = wp[4], w12 = wp[5];   // kh=1
                float w20 = wp[6], w21 = wp[7], w22 = wp[8];   // kh=2
                #pragma unroll
                for (int r = 0; r < 6; ++r) {
                    const float* row = s + (cseg * 4 + r) * 58 + h;
                    float v0 = row[0], v1 = row[1], v2 = row[2];  // kh = 0,1,2
                    float d0 = w00 * v0 + w10 * v1 + w20 * v2;    // kw=0
                    float d1 = w01 * v0 + w11 * v1 + w21 * v2;    // kw=1
                    float d2 = w02 * v0 + w12 * v1 + w22 * v2;    // kw=2
                    if (r      < 4)             acc[r]     += d0;
                    if (r - 1 >= 0 && r - 1 < 4) acc[r - 1] += d1;
                    if (r - 2 >= 0)             acc[r - 2] += d2;
                }
            }
        }
    }
    if (h < H_) {
        float g2 = __ldg(gam + 3) * rsqrtf(1.0f + 1e-5f);
        float b2 = __ldg(bet + 3);
        #pragma unroll
        for (int j = 0; j < 4; ++j) {
            int c = c0 + cseg * 4 + j;
            g_yw[((b * T_ + t) * C_ + c) * H_ + h] = sigmoidf_(acc[j] * g2 + b2);
        }
    }
}

// ---------------- K5: broadcast-combine -> out -------------------------------
__global__ void k_combine(float* __restrict__ out) {
    int gid = blockIdx.x * 256 + threadIdx.x;   // one float4 per thread
    if (gid >= BT * C_ * 784) return;
    int q     = gid % 784;
    int plane = gid / 784;
    int c  = plane % C_;
    int bt = plane / C_;
    int b = bt >> 3, t = bt & 7;
    int h  = q / 14;
    int w0 = (q - h * 14) * 4;

    const float4 yt4 = *(const float4*)(g_yt + (b * C_ + c) * HW + h * W_ + w0);
    const float4 yh4 = *(const float4*)(g_yh + ((b * T_ + t) * C_ + c) * W_ + w0);
    float yws = g_yw[((b * T_ + t) * C_ + c) * H_ + h];

    const float s3 = 1.0f / 3.0f;
    float4 o;
    o.x = (yt4.x + yh4.x + yws) * s3;
    o.y = (yt4.y + yh4.y + yws) * s3;
    o.z = (yt4.z + yh4.z + yws) * s3;
    o.w = (yt4.w + yh4.w + yws) * s3;
    ((float4*)out)[gid] = o;
}

// ---------------- launch -----------------------------------------------------
extern "C" void kernel_launch(void* const* d_in, const int* in_sizes, int n_in,
                              void* d_out, int out_size) {
    const float* x   = (const float*)d_in[0];
    const float* Wc  = (const float*)d_in[1];
    const float* Wt  = (const float*)d_in[2];
    const float* Wh  = (const float*)d_in[3];
    const float* Ww  = (const float*)d_in[4];
    const float* gam = (const float*)d_in[5];
    const float* bet = (const float*)d_in[6];
    float* out = (float*)d_out;

    k_cpool   <<<(BT * HW + 255) / 256, 256>>>(x);
    k_ycconv  <<<(BT * HW + 255) / 256, 256>>>(Wc, gam, bet);
    k_mainpool<<<B * C_, 256>>>(x);
    k_ytconv  <<<B * C_, 256>>>(Wt, gam, bet);
    k_yhconv  <<<1024, 256>>>(Wh, gam, bet);
    k_ywconv  <<<1024, 256>>>(Ww, gam, bet);
    k_combine <<<(BT * C_ * 784 + 255) / 256, 256>>>(out);
}

// round 5
// speedup vs baseline: 1.2826x; 1.0603x over previous
#include <cuda_runtime.h>
#include <math.h>
#include <float.h>

#define B   8
#define T_  8
#define C_  256
#define H_  56
#define W_  56
#define HW  3136      // 56*56
#define BT  64        // B*T_

// ---------------- scratch (device globals; no allocation allowed) ----------
__device__ float g_cmax [BT*HW];
__device__ float g_cmean[BT*HW];
__device__ float g_yc   [BT*HW];
__device__ float g_tmax [B*C_*HW];
__device__ float g_tmean[B*C_*HW];
__device__ float g_hmax [BT*C_*W_];
__device__ float g_hmean[BT*C_*W_];
__device__ float g_wmax [BT*C_*H_];
__device__ float g_wmean[BT*C_*H_];
__device__ float g_yt   [B*C_*HW];
__device__ float g_yh   [BT*C_*W_];
__device__ float g_yw   [BT*C_*H_];

__device__ __forceinline__ float sigmoidf_(float z) {
    return 1.0f / (1.0f + expf(-z));
}

// f32x2 packed math (Blackwell)
#define FFMA2(acc, w, v) asm("fma.rn.f32x2 %0, %1, %2, %0;" : "+l"(acc) : "l"(w), "l"(v))
#define PACK2(d, lo, hi) asm("mov.b64 %0, {%1, %2};" : "=l"(d) : "f"(lo), "f"(hi))

// ---------------- K1: channel pool (max/mean over C), float4 ----------------
__global__ void k_cpool(const float* __restrict__ x) {
    int idx = blockIdx.x * 128 + threadIdx.x;     // one float4 per thread
    if (idx >= BT * 784) return;
    int bt = idx / 784;
    int p4 = idx - bt * 784;
    const float4* px = (const float4*)(x + (size_t)bt * C_ * HW) + p4;
    float4 mx = make_float4(-FLT_MAX, -FLT_MAX, -FLT_MAX, -FLT_MAX);
    float4 sm = make_float4(0.f, 0.f, 0.f, 0.f);
    #pragma unroll 8
    for (int c = 0; c < C_; ++c) {
        float4 v = px[c * 784];
        mx.x = fmaxf(mx.x, v.x); mx.y = fmaxf(mx.y, v.y);
        mx.z = fmaxf(mx.z, v.z); mx.w = fmaxf(mx.w, v.w);
        sm.x += v.x; sm.y += v.y; sm.z += v.z; sm.w += v.w;
    }
    ((float4*)g_cmax)[idx] = mx;
    float4 mn = make_float4(sm.x * (1.f/C_), sm.y * (1.f/C_), sm.z * (1.f/C_), sm.w * (1.f/C_));
    ((float4*)g_cmean)[idx] = mn;
}

// ---------------- K2: yc = sigmoid(bn(conv3d over (T,h,w)))) ---------------
__global__ void k_ycconv(const float* __restrict__ Wc,
                         const float* __restrict__ gam,
                         const float* __restrict__ bet) {
    int idx = blockIdx.x * 256 + threadIdx.x;
    if (idx >= BT * HW) return;
    int bt = idx / HW;
    int p  = idx - bt * HW;
    int b = bt >> 3, t = bt & 7;
    int h = p / W_, w = p - h * W_;
    float acc = 0.0f;
    #pragma unroll
    for (int kd = 0; kd < 3; ++kd) {
        int tt = t + kd - 1;
        if (tt < 0 || tt >= T_) continue;
        #pragma unroll
        for (int kh = 0; kh < 3; ++kh) {
            int hh = h + kh - 1;
            if (hh < 0 || hh >= H_) continue;
            #pragma unroll
            for (int kw = 0; kw < 3; ++kw) {
                int ww = w + kw - 1;
                if (ww < 0 || ww >= W_) continue;
                int q = (b * T_ + tt) * HW + hh * W_ + ww;
                acc += g_cmax[q]  * __ldg(Wc +      kd * 9 + kh * 3 + kw)
                     + g_cmean[q] * __ldg(Wc + 27 + kd * 9 + kh * 3 + kw);
            }
        }
    }
    float g = __ldg(gam + 0) * rsqrtf(1.0f + 1e-5f);
    g_yc[idx] = sigmoidf_(acc * g + __ldg(bet + 0));
}

// ---------------- K3: main pool pass (float4 streaming phase) ---------------
__global__ void k_mainpool(const float* __restrict__ x) {
    int bc = blockIdx.x;
    int b = bc >> 8, c = bc & 255;
    __shared__ float s[HW];
    int tid = threadIdx.x;
    float4 tmx[4], tsm[4];
    #pragma unroll
    for (int k = 0; k < 4; ++k) {
        tmx[k] = make_float4(-FLT_MAX, -FLT_MAX, -FLT_MAX, -FLT_MAX);
        tsm[k] = make_float4(0.f, 0.f, 0.f, 0.f);
    }

    for (int t = 0; t < T_; ++t) {
        const float4* px4 = (const float4*)(x    + (size_t)((b * T_ + t) * C_ + c) * HW);
        const float4* py4 = (const float4*)(g_yc + (size_t)(b * T_ + t) * HW);
        #pragma unroll
        for (int k = 0; k < 4; ++k) {
            int p4 = tid + k * 256;
            if (k < 3 || p4 < 784) {
                float4 xv = px4[p4];
                float4 yv = py4[p4];
                float4 v = make_float4(xv.x*yv.x, xv.y*yv.y, xv.z*yv.z, xv.w*yv.w);
                ((float4*)s)[p4] = v;
                tmx[k].x = fmaxf(tmx[k].x, v.x); tmx[k].y = fmaxf(tmx[k].y, v.y);
                tmx[k].z = fmaxf(tmx[k].z, v.z); tmx[k].w = fmaxf(tmx[k].w, v.w);
                tsm[k].x += v.x; tsm[k].y += v.y; tsm[k].z += v.z; tsm[k].w += v.w;
            }
        }
        __syncthreads();
        int base = ((b * T_ + t) * C_ + c) * W_;
        if (tid < H_) {
            const float4* row = (const float4*)(s + tid * W_);
            float mx = -FLT_MAX, sm = 0.0f;
            #pragma unroll
            for (int i = 0; i < 14; ++i) {
                float4 v = row[i];
                mx = fmaxf(mx, fmaxf(fmaxf(v.x, v.y), fmaxf(v.z, v.w)));
                sm += (v.x + v.y) + (v.z + v.w);
            }
            g_wmax[base + tid]  = mx;
            g_wmean[base + tid] = sm * (1.0f / W_);
        } else if (tid >= 64 && tid < 64 + W_) {
            int w = tid - 64;
            float mx = -FLT_MAX, sm = 0.0f;
            #pragma unroll
            for (int h = 0; h < H_; ++h) { float v = s[h * W_ + w]; mx = fmaxf(mx, v); sm += v; }
            g_hmax[base + w]  = mx;
            g_hmean[base + w] = sm * (1.0f / H_);
        }
        __syncthreads();
    }
    int ob4 = (b * C_ + c) * 784;
    #pragma unroll
    for (int k = 0; k < 4; ++k) {
        int p4 = tid + k * 256;
        if (k < 3 || p4 < 784) {
            ((float4*)g_tmax)[ob4 + p4] = tmx[k];
            float4 mn = make_float4(tsm[k].x * (1.f/T_), tsm[k].y * (1.f/T_),
                                    tsm[k].z * (1.f/T_), tsm[k].w * (1.f/T_));
            ((float4*)g_tmean)[ob4 + p4] = mn;
        }
    }
}

// ---------------- K4a: yt conv over (c,h,w) — f32x2 + c-slide ring ----------
// grid 512: (b, ctile of 8 c, h-half of 28 rows). block 128.
// smem ring: 2 arrays x 3 c-planes x (30 rows x 64 padded cols). Halo pre-zeroed
// once; fills are div-free interior copies. Thread = w-pair x 7 output rows,
// accumulators packed f32x2; two aligned LDS.64 per (row, plane-pass).
__device__ __forceinline__ void fill_tile(float* tile, const float* gsrc, bool valid,
                                          int h0, int r_lo, int r_hi, int lane, int rgrp) {
    if (lane >= 56) return;
    for (int r = r_lo + rgrp; r <= r_hi; r += 2) {
        tile[r * 64 + 1 + lane] = valid ? gsrc[(h0 - 1 + r) * 56 + lane] : 0.f;
    }
}

__global__ __launch_bounds__(128) void k_ytconv(const float* __restrict__ Wt,
                                                const float* __restrict__ gam,
                                                const float* __restrict__ bet) {
    __shared__ float s[2][3][30 * 64];
    __shared__ float2 sw2[54];
    int bid  = blockIdx.x;
    int half = bid & 1, ct = (bid >> 1) & 31, b = bid >> 6;
    int c0 = ct * 8;
    int h0 = half * 28;
    int tid = threadIdx.x;

    // one-time pre-zero (halo cells stay zero forever)
    float* sall = &s[0][0][0];
    for (int i = tid; i < 2 * 3 * 30 * 64; i += 128) sall[i] = 0.f;
    if (tid < 54) { float v = __ldg(Wt + tid); sw2[tid] = make_float2(v, v); }
    __syncthreads();

    int lane = tid & 63, rgrp = tid >> 6;
    int r_lo = (h0 == 0) ? 1 : 0;
    int r_hi = (h0 == 0) ? 29 : 28;

    // preload planes c0-1 (slot 0) and c0 (slot 1)
    {
        bool v0 = (c0 - 1) >= 0;
        int cm = v0 ? c0 - 1 : 0;
        fill_tile(&s[0][0][0], g_tmax  + (size_t)(b * C_ + cm) * HW, v0, h0, r_lo, r_hi, lane, rgrp);
        fill_tile(&s[1][0][0], g_tmean + (size_t)(b * C_ + cm) * HW, v0, h0, r_lo, r_hi, lane, rgrp);
        fill_tile(&s[0][1][0], g_tmax  + (size_t)(b * C_ + c0) * HW, true, h0, r_lo, r_hi, lane, rgrp);
        fill_tile(&s[1][1][0], g_tmean + (size_t)(b * C_ + c0) * HW, true, h0, r_lo, r_hi, lane, rgrp);
    }

    int wpair = tid & 31, hseg = tid >> 5;   // 28 active wpairs, 4 hsegs x 7 rows
    int wc = wpair * 2;
    float g2 = __ldg(gam + 1) * rsqrtf(1.0f + 1e-5f);
    float b2 = __ldg(bet + 1);

    for (int ci = 0; ci < 8; ++ci) {
        int c = c0 + ci;
        // fill slot (ci+2)%3 with plane c+1
        {
            int cn = c + 1;
            bool vn = cn < C_;
            int cs = vn ? cn : 0;
            int snxt = (ci + 2) % 3;
            fill_tile(&s[0][snxt][0], g_tmax  + (size_t)(b * C_ + cs) * HW, vn, h0, r_lo, r_hi, lane, rgrp);
            fill_tile(&s[1][snxt][0], g_tmean + (size_t)(b * C_ + cs) * HW, vn, h0, r_lo, r_hi, lane, rgrp);
        }
        __syncthreads();

        if (wpair < 28) {
            unsigned long long acc[7];
            #pragma unroll
            for (int o = 0; o < 7; ++o) acc[o] = 0ull;
            #pragma unroll
            for (int ch = 0; ch < 2; ++ch) {
                #pragma unroll
                for (int dc = 0; dc < 3; ++dc) {
                    const float* tile = &s[ch][(ci + dc) % 3][0];
                    const unsigned long long* wp = (const unsigned long long*)&sw2[ch * 27 + dc * 9];
                    unsigned long long q0 = wp[0], q1 = wp[1], q2 = wp[2];
                    unsigned long long q3 = wp[3], q4 = wp[4], q5 = wp[5];
                    unsigned long long q6 = wp[6], q7 = wp[7], q8 = wp[8];
                    const float* basep = tile + hseg * 7 * 64 + wc;   // col idx of w-1 is wc
                    #pragma unroll
                    for (int r = 0; r < 9; ++r) {
                        // two 8B-aligned LDS.64 (wc is even, not mod-4: LDS.128 would trap)
                        float2 va = *(const float2*)(basep + r * 64);      // cols wc, wc+1
                        float2 vb = *(const float2*)(basep + r * 64 + 2);  // cols wc+2, wc+3
                        unsigned long long pm, p0, p1;
                        PACK2(pm, va.x, va.y);
                        PACK2(p0, va.y, vb.x);
                        PACK2(p1, vb.x, vb.y);
                        if (r < 7) {
                            FFMA2(acc[r], q0, pm); FFMA2(acc[r], q1, p0); FFMA2(acc[r], q2, p1);
                        }
                        if (r >= 1 && r <= 7) {
                            FFMA2(acc[r-1], q3, pm); FFMA2(acc[r-1], q4, p0); FFMA2(acc[r-1], q5, p1);
                        }
                        if (r >= 2) {
                            FFMA2(acc[r-2], q6, pm); FFMA2(acc[r-2], q7, p0); FFMA2(acc[r-2], q8, p1);
                        }
                    }
                }
            }
            float* outp = g_yt + (size_t)(b * C_ + c) * HW;
            #pragma unroll
            for (int o = 0; o < 7; ++o) {
                unsigned int lo, hi;
                asm("mov.b64 {%0,%1}, %2;" : "=r"(lo), "=r"(hi) : "l"(acc[o]));
                int h = h0 + hseg * 7 + o;
                float2 ov;
                ov.x = sigmoidf_(__uint_as_float(lo) * g2 + b2);
                ov.y = sigmoidf_(__uint_as_float(hi) * g2 + b2);
                *(float2*)(outp + h * 56 + wc) = ov;
            }
        }
        __syncthreads();
    }
}

// ---------------- K4b: yh conv over (T,c,w) ---------------------------------
__global__ void k_yhconv(const float* __restrict__ Wh,
                         const float* __restrict__ gam,
                         const float* __restrict__ bet) {
    int bid = blockIdx.x;
    int ct = bid & 15, t = (bid >> 4) & 7, b = bid >> 7;
    int c0 = ct * 16;
    __shared__ float s[18 * 58];
    __shared__ float sw[54];
    int tid  = threadIdx.x;
    int w    = tid & 63;
    int cseg = tid >> 6;
    if (tid < 54) sw[tid] = __ldg(Wh + tid);

    float acc[4];
    #pragma unroll
    for (int j = 0; j < 4; ++j) acc[j] = 0.0f;

    for (int ch = 0; ch < 2; ++ch) {
        const float* src = ch ? g_hmean : g_hmax;
        for (int kd = 0; kd < 3; ++kd) {
            int tt = t + kd - 1;
            if (tt < 0 || tt >= T_) continue;
            const float* pl = src + (size_t)(b * T_ + tt) * C_ * W_;
            __syncthreads();
            for (int i = tid; i < 18 * 58; i += 256) {
                int r  = i / 58, cl = i - r * 58;
                int cc = c0 - 1 + r, ww = cl - 1;
                s[i] = (cc >= 0 && cc < C_ && ww >= 0 && ww < W_)
                         ? pl[cc * W_ + ww] : 0.0f;
            }
            __syncthreads();
            if (w < W_) {
                const float* wp = sw + ch * 27 + kd * 9;
                float w00 = wp[0], w01 = wp[1], w02 = wp[2];
                float w10 = wp[3], w11 = wp[4], w12 = wp[5];
                float w20 = wp[6], w21 = wp[7], w22 = wp[8];
                #pragma unroll
                for (int r = 0; r < 6; ++r) {
                    const float* row = s + (cseg * 4 + r) * 58 + w;
                    float v0 = row[0], v1 = row[1], v2 = row[2];
                    float d0 = w00 * v0 + w01 * v1 + w02 * v2;
                    float d1 = w10 * v0 + w11 * v1 + w12 * v2;
                    float d2 = w20 * v0 + w21 * v1 + w22 * v2;
                    if (r      < 4)               acc[r]     += d0;
                    if (r - 1 >= 0 && r - 1 < 4)  acc[r - 1] += d1;
                    if (r - 2 >= 0)               acc[r - 2] += d2;
                }
            }
        }
    }
    if (w < W_) {
        float g2 = __ldg(gam + 2) * rsqrtf(1.0f + 1e-5f);
        float b2 = __ldg(bet + 2);
        #pragma unroll
        for (int j = 0; j < 4; ++j) {
            int c = c0 + cseg * 4 + j;
            g_yh[((b * T_ + t) * C_ + c) * W_ + w] = sigmoidf_(acc[j] * g2 + b2);
        }
    }
}

// ---------------- K4c: yw conv over (T,h,c) ---------------------------------
__global__ void k_ywconv(const float* __restrict__ Ww,
                         const float* __restrict__ gam,
                         const float* __restrict__ bet) {
    int bid = blockIdx.x;
    int ct = bid & 15, t = (bid >> 4) & 7, b = bid >> 7;
    int c0 = ct * 16;
    __shared__ float s[18 * 58];
    __shared__ float sw[54];
    int tid  = threadIdx.x;
    int h    = tid & 63;
    int cseg = tid >> 6;
    if (tid < 54) sw[tid] = __ldg(Ww + tid);

    float acc[4];
    #pragma unroll
    for (int j = 0; j < 4; ++j) acc[j] = 0.0f;

    for (int ch = 0; ch < 2; ++ch) {
        const float* src = ch ? g_wmean : g_wmax;
        for (int kd = 0; kd < 3; ++kd) {
            int tt = t + kd - 1;
            if (tt < 0 || tt >= T_) continue;
            const float* pl = src + (size_t)(b * T_ + tt) * C_ * H_;
            __syncthreads();
            for (int i = tid; i < 18 * 58; i += 256) {
                int r  = i / 58, cl = i - r * 58;
                int cc = c0 - 1 + r, hh = cl - 1;
                s[i] = (cc >= 0 && cc < C_ && hh >= 0 && hh < H_)
                         ? pl[cc * H_ + hh] : 0.0f;
            }
            __syncthreads();
            if (h < H_) {
                const float* wp = sw + ch * 27 + kd * 9;
                float w00 = wp[0], w01 = wp[1], w02 = wp[2];
                float w10 = wp[3], w11 = wp[4], w12 = wp[5];
                float w20 = wp[6], w21 = wp[7], w22 = wp[8];
                #pragma unroll
                for (int r = 0; r < 6; ++r) {
                    const float* row = s + (cseg * 4 + r) * 58 + h;
                    float v0 = row[0], v1 = row[1], v2 = row[2];
                    float d0 = w00 * v0 + w10 * v1 + w20 * v2;
                    float d1 = w01 * v0 + w11 * v1 + w21 * v2;
                    float d2 = w02 * v0 + w12 * v1 + w22 * v2;
                    if (r      < 4)               acc[r]     += d0;
                    if (r - 1 >= 0 && r - 1 < 4)  acc[r - 1] += d1;
                    if (r - 2 >= 0)               acc[r - 2] += d2;
                }
            }
        }
    }
    if (h < H_) {
        float g2 = __ldg(gam + 3) * rsqrtf(1.0f + 1e-5f);
        float b2 = __ldg(bet + 3);
        #pragma unroll
        for (int j = 0; j < 4; ++j) {
            int c = c0 + cseg * 4 + j;
            g_yw[((b * T_ + t) * C_ + c) * H_ + h] = sigmoidf_(acc[j] * g2 + b2);
        }
    }
}

// ---------------- K5: broadcast-combine -> out -------------------------------
__global__ void k_combine(float* __restrict__ out) {
    int gid = blockIdx.x * 256 + threadIdx.x;   // one float4 per thread
    if (gid >= BT * C_ * 784) return;
    int q     = gid % 784;
    int plane = gid / 784;
    int c  = plane % C_;
    int bt = plane / C_;
    int b = bt >> 3, t = bt & 7;
    int h  = q / 14;
    int w0 = (q - h * 14) * 4;

    const float4 yt4 = *(const float4*)(g_yt + (b * C_ + c) * HW + h * W_ + w0);
    const float4 yh4 = *(const float4*)(g_yh + ((b * T_ + t) * C_ + c) * W_ + w0);
    float yws = g_yw[((b * T_ + t) * C_ + c) * H_ + h];

    const float s3 = 1.0f / 3.0f;
    float4 o;
    o.x = (yt4.x + yh4.x + yws) * s3;
    o.y = (yt4.y + yh4.y + yws) * s3;
    o.z = (yt4.z + yh4.z + yws) * s3;
    o.w = (yt4.w + yh4.w + yws) * s3;
    ((float4*)out)[gid] = o;
}

// ---------------- launch -----------------------------------------------------
extern "C" void kernel_launch(void* const* d_in, const int* in_sizes, int n_in,
                              void* d_out, int out_size) {
    const float* x   = (const float*)d_in[0];
    const float* Wc  = (const float*)d_in[1];
    const float* Wt  = (const float*)d_in[2];
    const float* Wh  = (const float*)d_in[3];
    const float* Ww  = (const float*)d_in[4];
    const float* gam = (const float*)d_in[5];
    const float* bet = (const float*)d_in[6];
    float* out = (float*)d_out;

    k_cpool   <<<(BT * 784 + 127) / 128, 128>>>(x);
    k_ycconv  <<<(BT * HW + 255) / 256, 256>>>(Wc, gam, bet);
    k_mainpool<<<B * C_, 256>>>(x);
    k_ytconv  <<<512, 128>>>(Wt, gam, bet);
    k_yhconv  <<<1024, 256>>>(Wh, gam, bet);
    k_ywconv  <<<1024, 256>>>(Ww, gam, bet);
    k_combine <<<(BT * C_ * 784 + 255) / 256, 256>>>(out);
}